// round 2
// baseline (speedup 1.0000x reference)
#include <cuda_runtime.h>
#include <cuda_bf16.h>
#include <math.h>

// ---------------------------------------------------------------------------
// MiniGPT forward, fp32 baseline.
// B=4, T=1024, C=1024, H=16, HD=64, L=8, V=32000.
// ---------------------------------------------------------------------------

#define BATCH 4
#define TLEN 1024
#define CDIM 1024
#define NHEAD 16
#define HDIM 64
#define NLAYER 8
#define VOCAB 32000
#define NTOK (BATCH * TLEN)          // 4096
#define FF (4 * CDIM)                // 4096

// ---------------- device scratch (static, no allocation) -------------------
__device__ float g_x[NTOK * CDIM];                 // residual stream   16 MB
__device__ float g_h[NTOK * CDIM];                 // LN output         16 MB
__device__ float g_qkv[NTOK * 3 * CDIM];           // fused QKV         48 MB
__device__ float g_o[NTOK * CDIM];                 // attn out          16 MB
__device__ float g_ff[NTOK * FF];                  // MLP hidden        64 MB
__device__ float g_scores[(size_t)BATCH * NHEAD * TLEN * TLEN]; // 256 MB
__device__ float g_wqkv[(size_t)NLAYER * CDIM * 3 * CDIM];      //  96 MB

// ---------------------------------------------------------------------------
// Pack wq/wk/wv [L,H,C,HD] -> fused [L, C, 3C] with col j = h*64+d (+1024 K, +2048 V)
// ---------------------------------------------------------------------------
__global__ void pack_qkv_kernel(const float* __restrict__ wq,
                                const float* __restrict__ wk,
                                const float* __restrict__ wv,
                                float* __restrict__ wqkv) {
    size_t i = (size_t)blockIdx.x * blockDim.x + threadIdx.x;
    const size_t total = (size_t)NLAYER * NHEAD * CDIM * HDIM; // 8,388,608
    if (i >= total) return;
    int d = (int)(i & 63);
    int c = (int)((i >> 6) & 1023);
    int h = (int)((i >> 16) & 15);
    int l = (int)(i >> 20);
    size_t dst = ((size_t)l * CDIM + c) * (3 * CDIM) + h * HDIM + d;
    wqkv[dst]            = wq[i];
    wqkv[dst + CDIM]     = wk[i];
    wqkv[dst + 2 * CDIM] = wv[i];
}

// ---------------------------------------------------------------------------
// Embedding: x[b,t,:] = tok_emb[idx[b,t],:] + pos_emb[t,:]
// ---------------------------------------------------------------------------
__global__ void embed_kernel(const int* __restrict__ idx,
                             const float* __restrict__ tok,
                             const float* __restrict__ pos,
                             float* __restrict__ x) {
    int row = blockIdx.x;                 // 0..4095
    int t = row & (TLEN - 1);
    int token = idx[row];
    const float4* te = (const float4*)(tok + (size_t)token * CDIM);
    const float4* pe = (const float4*)(pos + (size_t)t * CDIM);
    float4* xo = (float4*)(x + (size_t)row * CDIM);
    int i = threadIdx.x;                  // 256 threads x float4 = 1024
    float4 a = te[i], b = pe[i];
    a.x += b.x; a.y += b.y; a.z += b.z; a.w += b.w;
    xo[i] = a;
}

// ---------------------------------------------------------------------------
// LayerNorm over rows of length 1024. 256 threads per row.
// ---------------------------------------------------------------------------
__global__ void ln_kernel(const float* __restrict__ x,
                          const float* __restrict__ g,
                          const float* __restrict__ b,
                          float* __restrict__ out) {
    int row = blockIdx.x;
    int tid = threadIdx.x;
    const float4* xr = (const float4*)(x + (size_t)row * CDIM);
    float4 v = xr[tid];
    float s  = v.x + v.y + v.z + v.w;
    float ss = v.x * v.x + v.y * v.y + v.z * v.z + v.w * v.w;
    #pragma unroll
    for (int o = 16; o > 0; o >>= 1) {
        s  += __shfl_xor_sync(0xffffffffu, s,  o);
        ss += __shfl_xor_sync(0xffffffffu, ss, o);
    }
    __shared__ float sm[8], sm2[8];
    int w = tid >> 5, lane = tid & 31;
    if (lane == 0) { sm[w] = s; sm2[w] = ss; }
    __syncthreads();
    s = 0.f; ss = 0.f;
    #pragma unroll
    for (int i = 0; i < 8; i++) { s += sm[i]; ss += sm2[i]; }
    float mean = s * (1.0f / CDIM);
    float var  = ss * (1.0f / CDIM) - mean * mean;
    float rstd = rsqrtf(var + 1e-5f);
    float4 gv = ((const float4*)g)[tid];
    float4 bv = ((const float4*)b)[tid];
    float4 o;
    o.x = (v.x - mean) * rstd * gv.x + bv.x;
    o.y = (v.y - mean) * rstd * gv.y + bv.y;
    o.z = (v.z - mean) * rstd * gv.z + bv.z;
    o.w = (v.w - mean) * rstd * gv.w + bv.w;
    ((float4*)(out + (size_t)row * CDIM))[tid] = o;
}

// ---------------------------------------------------------------------------
// SGEMM: C[M,N] = A[M,K] * B[K,N]  (+bias[n]) (+res) (relu)
// BM=BN=128, BK=8, TM=TN=8, 256 threads. All dims multiples of tile sizes.
// ---------------------------------------------------------------------------
__global__ __launch_bounds__(256)
void sgemm_kernel(const float* __restrict__ A, const float* __restrict__ B,
                  float* __restrict__ C, int M, int N, int K,
                  const float* __restrict__ bias,
                  const float* __restrict__ res, int relu) {
    __shared__ float As[8][128];
    __shared__ float Bs[8][128];
    int bx = blockIdx.x;     // N tile
    int by = blockIdx.y;     // M tile
    int tid = threadIdx.x;
    int tr = tid >> 4;       // 0..15  (row group of 8)
    int tc = tid & 15;       // 0..15  (col group of 8)

    int arow = tid >> 1;            // 0..127
    int acol = (tid & 1) * 4;       // 0 or 4
    int brow = tid >> 5;            // 0..7
    int bcol = (tid & 31) * 4;      // 0..124

    const float* Abase = A + (size_t)(by * 128) * K;
    const float* Bbase = B + (size_t)bx * 128;

    float acc[8][8];
    #pragma unroll
    for (int i = 0; i < 8; i++)
        #pragma unroll
        for (int j = 0; j < 8; j++) acc[i][j] = 0.f;

    for (int k0 = 0; k0 < K; k0 += 8) {
        float4 av = *(const float4*)(Abase + (size_t)arow * K + k0 + acol);
        As[acol + 0][arow] = av.x;
        As[acol + 1][arow] = av.y;
        As[acol + 2][arow] = av.z;
        As[acol + 3][arow] = av.w;
        float4 bv = *(const float4*)(Bbase + (size_t)(k0 + brow) * N + bcol);
        *(float4*)&Bs[brow][bcol] = bv;
        __syncthreads();
        #pragma unroll
        for (int k = 0; k < 8; k++) {
            float4 a0 = *(const float4*)&As[k][tr * 8];
            float4 a1 = *(const float4*)&As[k][tr * 8 + 4];
            float4 b0 = *(const float4*)&Bs[k][tc * 8];
            float4 b1 = *(const float4*)&Bs[k][tc * 8 + 4];
            float ar[8] = {a0.x, a0.y, a0.z, a0.w, a1.x, a1.y, a1.z, a1.w};
            float br[8] = {b0.x, b0.y, b0.z, b0.w, b1.x, b1.y, b1.z, b1.w};
            #pragma unroll
            for (int i = 0; i < 8; i++)
                #pragma unroll
                for (int j = 0; j < 8; j++)
                    acc[i][j] = fmaf(ar[i], br[j], acc[i][j]);
        }
        __syncthreads();
    }

    // epilogue
    int col0 = bx * 128 + tc * 8;
    float bload[8];
    if (bias) {
        float4 q0 = *(const float4*)(bias + col0);
        float4 q1 = *(const float4*)(bias + col0 + 4);
        bload[0]=q0.x; bload[1]=q0.y; bload[2]=q0.z; bload[3]=q0.w;
        bload[4]=q1.x; bload[5]=q1.y; bload[6]=q1.z; bload[7]=q1.w;
    } else {
        #pragma unroll
        for (int j = 0; j < 8; j++) bload[j] = 0.f;
    }
    size_t cbase = (size_t)(by * 128 + tr * 8) * N + col0;
    #pragma unroll
    for (int i = 0; i < 8; i++) {
        float v[8];
        #pragma unroll
        for (int j = 0; j < 8; j++) v[j] = acc[i][j] + bload[j];
        if (res) {
            float4 e0 = *(const float4*)(res + cbase + (size_t)i * N);
            float4 e1 = *(const float4*)(res + cbase + (size_t)i * N + 4);
            v[0]+=e0.x; v[1]+=e0.y; v[2]+=e0.z; v[3]+=e0.w;
            v[4]+=e1.x; v[5]+=e1.y; v[6]+=e1.z; v[7]+=e1.w;
        }
        if (relu) {
            #pragma unroll
            for (int j = 0; j < 8; j++) v[j] = fmaxf(v[j], 0.f);
        }
        float4 s0 = {v[0], v[1], v[2], v[3]};
        float4 s1 = {v[4], v[5], v[6], v[7]};
        *(float4*)(C + cbase + (size_t)i * N)     = s0;
        *(float4*)(C + cbase + (size_t)i * N + 4) = s1;
    }
}

// ---------------------------------------------------------------------------
// QK^T scores: 64x64 tile per block, only lower-triangular tiles.
// scores[bh, t, s] = 0.125 * sum_d q[b,t,h,d] * k[b,s,h,d]
// ---------------------------------------------------------------------------
__global__ __launch_bounds__(256)
void qk_kernel(const float* __restrict__ qkv, float* __restrict__ scores) {
    int st = blockIdx.x, tt = blockIdx.y;
    if (st > tt) return;
    int bh = blockIdx.z;
    int b = bh >> 4, h = bh & 15;
    const float* Qb = qkv + (size_t)b * TLEN * (3 * CDIM) + h * HDIM;
    const float* Kb = Qb + CDIM;
    float* S = scores + (size_t)bh * TLEN * TLEN;
    __shared__ float Qs[64][64];   // [d][t]
    __shared__ float Ks[64][64];   // [d][s]
    int tid = threadIdx.x;
    int r = tid >> 2;        // 0..63
    int cg = tid & 3;        // 0..3
    int t0 = tt * 64, s0 = st * 64;
    #pragma unroll
    for (int i = 0; i < 4; i++) {
        int c4 = cg + i * 4;         // float4 index 0..15
        float4 qv = *(const float4*)(Qb + (size_t)(t0 + r) * (3 * CDIM) + c4 * 4);
        Qs[c4 * 4 + 0][r] = qv.x; Qs[c4 * 4 + 1][r] = qv.y;
        Qs[c4 * 4 + 2][r] = qv.z; Qs[c4 * 4 + 3][r] = qv.w;
        float4 kv = *(const float4*)(Kb + (size_t)(s0 + r) * (3 * CDIM) + c4 * 4);
        Ks[c4 * 4 + 0][r] = kv.x; Ks[c4 * 4 + 1][r] = kv.y;
        Ks[c4 * 4 + 2][r] = kv.z; Ks[c4 * 4 + 3][r] = kv.w;
    }
    __syncthreads();
    int trow = tid >> 4, tcol = tid & 15;
    float acc[4][4];
    #pragma unroll
    for (int i = 0; i < 4; i++)
        #pragma unroll
        for (int j = 0; j < 4; j++) acc[i][j] = 0.f;
    #pragma unroll 8
    for (int d = 0; d < 64; d++) {
        float4 a = *(const float4*)&Qs[d][trow * 4];
        float4 bb = *(const float4*)&Ks[d][tcol * 4];
        float ar[4] = {a.x, a.y, a.z, a.w};
        float br[4] = {bb.x, bb.y, bb.z, bb.w};
        #pragma unroll
        for (int i = 0; i < 4; i++)
            #pragma unroll
            for (int j = 0; j < 4; j++)
                acc[i][j] = fmaf(ar[i], br[j], acc[i][j]);
    }
    const float scale = 0.125f;
    #pragma unroll
    for (int i = 0; i < 4; i++) {
        float4 s4 = {acc[i][0] * scale, acc[i][1] * scale,
                     acc[i][2] * scale, acc[i][3] * scale};
        *(float4*)(S + (size_t)(t0 + trow * 4 + i) * TLEN + s0 + tcol * 4) = s4;
    }
}

// ---------------------------------------------------------------------------
// Causal softmax in-place. One warp per row; zeros written for s > t.
// ---------------------------------------------------------------------------
__global__ void softmax_kernel(float* __restrict__ scores) {
    int warp = threadIdx.x >> 5, lane = threadIdx.x & 31;
    size_t row = (size_t)blockIdx.x * 4 + warp;     // 0..65535
    int t = (int)(row & (TLEN - 1));
    float* S = scores + row * TLEN;
    float m = -1e30f, l = 0.f;
    for (int s = lane; s <= t; s += 32) {
        float v = S[s];
        float nm = fmaxf(m, v);
        l = l * __expf(m - nm) + __expf(v - nm);
        m = nm;
    }
    #pragma unroll
    for (int o = 16; o > 0; o >>= 1) {
        float m2 = __shfl_xor_sync(0xffffffffu, m, o);
        float l2 = __shfl_xor_sync(0xffffffffu, l, o);
        float nm = fmaxf(m, m2);
        l = l * __expf(m - nm) + l2 * __expf(m2 - nm);
        m = nm;
    }
    float inv = 1.f / l;
    for (int s = lane; s < TLEN; s += 32) {
        float v = (s <= t) ? __expf(S[s] - m) * inv : 0.f;
        S[s] = v;
    }
}

// ---------------------------------------------------------------------------
// AV: o[b,t,h,d] = sum_s p[bh,t,s] * v[b,s,h,d]. 64(t) x 64(d) per block,
// causal K loop (s only up to end of this t-tile).
// ---------------------------------------------------------------------------
__global__ __launch_bounds__(256)
void av_kernel(const float* __restrict__ scores, const float* __restrict__ qkv,
               float* __restrict__ o) {
    int tt = blockIdx.x;
    int bh = blockIdx.y;
    int b = bh >> 4, h = bh & 15;
    const float* P = scores + (size_t)bh * TLEN * TLEN + (size_t)tt * 64 * TLEN;
    const float* V = qkv + (size_t)b * TLEN * (3 * CDIM) + 2 * CDIM + h * HDIM;
    int tid = threadIdx.x;
    __shared__ float Ps[64][64];   // [s][t]
    __shared__ float Vs[64][64];   // [s][d]
    int r = tid >> 2, cg = tid & 3;
    int trow = tid >> 4, tcol = tid & 15;
    float acc[4][4];
    #pragma unroll
    for (int i = 0; i < 4; i++)
        #pragma unroll
        for (int j = 0; j < 4; j++) acc[i][j] = 0.f;
    int nk = (tt + 1) * 64;
    for (int s0 = 0; s0 < nk; s0 += 64) {
        #pragma unroll
        for (int i = 0; i < 4; i++) {
            int c4 = cg + i * 4;
            float4 pv = *(const float4*)(P + (size_t)r * TLEN + s0 + c4 * 4);
            Ps[c4 * 4 + 0][r] = pv.x; Ps[c4 * 4 + 1][r] = pv.y;
            Ps[c4 * 4 + 2][r] = pv.z; Ps[c4 * 4 + 3][r] = pv.w;
            float4 vv = *(const float4*)(V + (size_t)(s0 + r) * (3 * CDIM) + c4 * 4);
            *(float4*)&Vs[r][c4 * 4] = vv;
        }
        __syncthreads();
        #pragma unroll 8
        for (int s = 0; s < 64; s++) {
            float4 a = *(const float4*)&Ps[s][trow * 4];
            float4 bb = *(const float4*)&Vs[s][tcol * 4];
            float ar[4] = {a.x, a.y, a.z, a.w};
            float br[4] = {bb.x, bb.y, bb.z, bb.w};
            #pragma unroll
            for (int i = 0; i < 4; i++)
                #pragma unroll
                for (int j = 0; j < 4; j++)
                    acc[i][j] = fmaf(ar[i], br[j], acc[i][j]);
        }
        __syncthreads();
    }
    int t0 = tt * 64;
    #pragma unroll
    for (int i = 0; i < 4; i++) {
        float4 s4 = {acc[i][0], acc[i][1], acc[i][2], acc[i][3]};
        *(float4*)(o + (size_t)(b * TLEN + t0 + trow * 4 + i) * CDIM
                     + h * HDIM + tcol * 4) = s4;
    }
}

// ---------------------------------------------------------------------------
// Host orchestration
// ---------------------------------------------------------------------------
extern "C" void kernel_launch(void* const* d_in, const int* in_sizes, int n_in,
                              void* d_out, int out_size) {
    const int*   idx   = (const int*)d_in[0];
    const float* tok   = (const float*)d_in[1];
    const float* pos   = (const float*)d_in[2];
    const float* wq    = (const float*)d_in[3];
    const float* wk    = (const float*)d_in[4];
    const float* wv    = (const float*)d_in[5];
    const float* wproj = (const float*)d_in[6];
    const float* bproj = (const float*)d_in[7];
    const float* ln1g  = (const float*)d_in[8];
    const float* ln1b  = (const float*)d_in[9];
    const float* ln2g  = (const float*)d_in[10];
    const float* ln2b  = (const float*)d_in[11];
    const float* w1    = (const float*)d_in[12];
    const float* b1    = (const float*)d_in[13];
    const float* w2    = (const float*)d_in[14];
    const float* b2    = (const float*)d_in[15];
    const float* lnfg  = (const float*)d_in[16];
    const float* lnfb  = (const float*)d_in[17];
    const float* wlm   = (const float*)d_in[18];
    const float* blm   = (const float*)d_in[19];
    float* out = (float*)d_out;

    float *px, *ph, *pqkv, *po, *pff, *pscores, *pwqkv;
    cudaGetSymbolAddress((void**)&px, g_x);
    cudaGetSymbolAddress((void**)&ph, g_h);
    cudaGetSymbolAddress((void**)&pqkv, g_qkv);
    cudaGetSymbolAddress((void**)&po, g_o);
    cudaGetSymbolAddress((void**)&pff, g_ff);
    cudaGetSymbolAddress((void**)&pscores, g_scores);
    cudaGetSymbolAddress((void**)&pwqkv, g_wqkv);

    // pack fused QKV weights
    {
        size_t total = (size_t)NLAYER * NHEAD * CDIM * HDIM;
        pack_qkv_kernel<<<(unsigned)((total + 255) / 256), 256>>>(wq, wk, wv, pwqkv);
    }
    // embeddings
    embed_kernel<<<NTOK, 256>>>(idx, tok, pos, px);

    for (int l = 0; l < NLAYER; l++) {
        // LN1
        ln_kernel<<<NTOK, 256>>>(px, ln1g + (size_t)l * CDIM, ln1b + (size_t)l * CDIM, ph);
        // QKV GEMM: [4096,1024] x [1024,3072]
        {
            dim3 grid(3 * CDIM / 128, NTOK / 128);
            sgemm_kernel<<<grid, 256>>>(ph, pwqkv + (size_t)l * CDIM * 3 * CDIM,
                                        pqkv, NTOK, 3 * CDIM, CDIM,
                                        nullptr, nullptr, 0);
        }
        // scores (lower-triangular tiles only)
        {
            dim3 grid(TLEN / 64, TLEN / 64, BATCH * NHEAD);
            qk_kernel<<<grid, 256>>>(pqkv, pscores);
        }
        // causal softmax (in place)
        softmax_kernel<<<BATCH * NHEAD * TLEN / 4, 128>>>(pscores);
        // AV
        {
            dim3 grid(TLEN / 64, BATCH * NHEAD);
            av_kernel<<<grid, 256>>>(pscores, pqkv, po);
        }
        // proj + bias + residual -> x
        {
            dim3 grid(CDIM / 128, NTOK / 128);
            sgemm_kernel<<<grid, 256>>>(po, wproj + (size_t)l * CDIM * CDIM, px,
                                        NTOK, CDIM, CDIM,
                                        bproj + (size_t)l * CDIM, px, 0);
        }
        // LN2
        ln_kernel<<<NTOK, 256>>>(px, ln2g + (size_t)l * CDIM, ln2b + (size_t)l * CDIM, ph);
        // MLP up + relu
        {
            dim3 grid(FF / 128, NTOK / 128);
            sgemm_kernel<<<grid, 256>>>(ph, w1 + (size_t)l * CDIM * FF, pff,
                                        NTOK, FF, CDIM,
                                        b1 + (size_t)l * FF, nullptr, 1);
        }
        // MLP down + bias + residual -> x
        {
            dim3 grid(CDIM / 128, NTOK / 128);
            sgemm_kernel<<<grid, 256>>>(pff, w2 + (size_t)l * FF * CDIM, px,
                                        NTOK, CDIM, FF,
                                        b2 + (size_t)l * CDIM, px, 0);
        }
    }
    // final LN
    ln_kernel<<<NTOK, 256>>>(px, lnfg, lnfb, ph);
    // LM head: [4096,1024] x [1024,32000]
    {
        dim3 grid(VOCAB / 128, NTOK / 128);
        sgemm_kernel<<<grid, 256>>>(ph, wlm, out, NTOK, VOCAB, CDIM,
                                    blm, nullptr, 0);
    }
}

// round 4
// speedup vs baseline: 2.9280x; 2.9280x over previous
#include <cuda_runtime.h>
#include <cuda_bf16.h>
#include <cstdint>
#include <math.h>

#define BATCH 4
#define TLEN 1024
#define CDIM 1024
#define NHEAD 16
#define HDIM 64
#define NLAYER 8
#define VOCAB 32000
#define NTOK (BATCH * TLEN)
#define FF (4 * CDIM)

// ---------------- device scratch ----------------
__device__ float g_x[NTOK * CDIM];
__device__ float g_qkv[NTOK * 3 * CDIM];
__device__ float g_scores[(size_t)BATCH * NHEAD * TLEN * TLEN];
__device__ unsigned short g_hb_h[NTOK * CDIM], g_hb_l[NTOK * CDIM];
__device__ unsigned short g_ob_h[NTOK * CDIM], g_ob_l[NTOK * CDIM];
__device__ unsigned short g_ffb_h[(size_t)NTOK * FF], g_ffb_l[(size_t)NTOK * FF];
__device__ unsigned short g_wqkv_h[(size_t)NLAYER * 3 * CDIM * CDIM], g_wqkv_l[(size_t)NLAYER * 3 * CDIM * CDIM];
__device__ unsigned short g_wproj_h[(size_t)NLAYER * CDIM * CDIM], g_wproj_l[(size_t)NLAYER * CDIM * CDIM];
__device__ unsigned short g_w1_h[(size_t)NLAYER * FF * CDIM], g_w1_l[(size_t)NLAYER * FF * CDIM];
__device__ unsigned short g_w2_h[(size_t)NLAYER * CDIM * FF], g_w2_l[(size_t)NLAYER * CDIM * FF];
__device__ unsigned short g_wlm_h[(size_t)VOCAB * CDIM], g_wlm_l[(size_t)VOCAB * CDIM];

// ---------------- helpers ----------------
__device__ __forceinline__ uint32_t cvta_s(const void* p) {
    uint32_t a;
    asm("{ .reg .u64 t; cvta.to.shared.u64 t, %1; cvt.u32.u64 %0, t; }" : "=r"(a) : "l"(p));
    return a;
}
#define CP_ASYNC16(dst, src) \
    asm volatile("cp.async.cg.shared.global [%0], [%1], 16;" :: "r"(dst), "l"(src))
#define CP_COMMIT() asm volatile("cp.async.commit_group;" ::: "memory")
#define CP_WAIT(n)  asm volatile("cp.async.wait_group %0;" :: "n"(n) : "memory")

__device__ __forceinline__ void ldm_x4(uint32_t* r, uint32_t addr) {
    asm volatile("ldmatrix.sync.aligned.m8n8.x4.shared.b16 {%0,%1,%2,%3}, [%4];"
                 : "=r"(r[0]), "=r"(r[1]), "=r"(r[2]), "=r"(r[3]) : "r"(addr));
}
__device__ __forceinline__ void ldm_x2(uint32_t* r, uint32_t addr) {
    asm volatile("ldmatrix.sync.aligned.m8n8.x2.shared.b16 {%0,%1}, [%2];"
                 : "=r"(r[0]), "=r"(r[1]) : "r"(addr));
}
__device__ __forceinline__ void mma_bf16(float* d, const uint32_t* a, const uint32_t* b) {
    asm volatile(
        "mma.sync.aligned.m16n8k16.row.col.f32.bf16.bf16.f32 "
        "{%0,%1,%2,%3}, {%4,%5,%6,%7}, {%8,%9}, {%0,%1,%2,%3};"
        : "+f"(d[0]), "+f"(d[1]), "+f"(d[2]), "+f"(d[3])
        : "r"(a[0]), "r"(a[1]), "r"(a[2]), "r"(a[3]), "r"(b[0]), "r"(b[1]));
}
__device__ __forceinline__ void bsplit(float v, unsigned short& h, unsigned short& l) {
    __nv_bfloat16 hb = __float2bfloat16(v);
    __nv_bfloat16 lb = __float2bfloat16(v - __bfloat162float(hb));
    h = __bfloat16_as_ushort(hb);
    l = __bfloat16_as_ushort(lb);
}

// ---------------- weight prep (transpose + hi/lo split) ----------------
__global__ void tsplit_qkv_kernel(const float* __restrict__ wq, const float* __restrict__ wk,
                                  const float* __restrict__ wv,
                                  unsigned short* __restrict__ dh, unsigned short* __restrict__ dl) {
    __shared__ float t[32][33];
    int n0 = blockIdx.x * 32, k0 = blockIdx.y * 32, l = blockIdx.z;
    int sel = n0 >> 10;
    const float* src = sel == 0 ? wq : (sel == 1 ? wk : wv);
    int within = n0 & 1023;
    int h = within >> 6, d0 = within & 63;
    const float* sp = src + ((size_t)(l * 16 + h) * 1024 + k0) * 64 + d0;
    int tx = threadIdx.x, ty = threadIdx.y;
    #pragma unroll
    for (int i = 0; i < 4; i++) t[ty + i * 8][tx] = sp[(size_t)(ty + i * 8) * 64 + tx];
    __syncthreads();
    size_t ob = (size_t)l * 3072 * 1024;
    #pragma unroll
    for (int i = 0; i < 4; i++) {
        int n = n0 + ty + i * 8, k = k0 + tx;
        unsigned short hh, ll;
        bsplit(t[tx][ty + i * 8], hh, ll);
        dh[ob + (size_t)n * 1024 + k] = hh;
        dl[ob + (size_t)n * 1024 + k] = ll;
    }
}
__global__ void tsplit_mat_kernel(const float* __restrict__ src,
                                  unsigned short* __restrict__ dh, unsigned short* __restrict__ dl,
                                  int K, int N) {
    __shared__ float t[32][33];
    int n0 = blockIdx.x * 32, k0 = blockIdx.y * 32;
    size_t l = blockIdx.z;
    const float* sp = src + l * (size_t)K * N;
    int tx = threadIdx.x, ty = threadIdx.y;
    #pragma unroll
    for (int i = 0; i < 4; i++) t[ty + i * 8][tx] = sp[(size_t)(k0 + ty + i * 8) * N + n0 + tx];
    __syncthreads();
    size_t ob = l * (size_t)K * N;
    #pragma unroll
    for (int i = 0; i < 4; i++) {
        int n = n0 + ty + i * 8, k = k0 + tx;
        unsigned short hh, ll;
        bsplit(t[tx][ty + i * 8], hh, ll);
        dh[ob + (size_t)n * K + k] = hh;
        dl[ob + (size_t)n * K + k] = ll;
    }
}

// ---------------- embed ----------------
__global__ void embed_kernel(const int* __restrict__ idx, const float* __restrict__ tok,
                             const float* __restrict__ pos, float* __restrict__ x) {
    int row = blockIdx.x;
    int t = row & (TLEN - 1);
    int token = idx[row];
    const float4* te = (const float4*)(tok + (size_t)token * CDIM);
    const float4* pe = (const float4*)(pos + (size_t)t * CDIM);
    float4* xo = (float4*)(x + (size_t)row * CDIM);
    int i = threadIdx.x;
    float4 a = te[i], b = pe[i];
    a.x += b.x; a.y += b.y; a.z += b.z; a.w += b.w;
    xo[i] = a;
}

// ---------------- LayerNorm -> bf16 hi/lo ----------------
__global__ void ln_kernel(const float* __restrict__ x, const float* __restrict__ g,
                          const float* __restrict__ b,
                          unsigned short* __restrict__ oh, unsigned short* __restrict__ ol) {
    int row = blockIdx.x;
    int tid = threadIdx.x;
    float4 v = ((const float4*)(x + (size_t)row * CDIM))[tid];
    float s = v.x + v.y + v.z + v.w;
    float ss = v.x * v.x + v.y * v.y + v.z * v.z + v.w * v.w;
    #pragma unroll
    for (int o = 16; o > 0; o >>= 1) {
        s += __shfl_xor_sync(0xffffffffu, s, o);
        ss += __shfl_xor_sync(0xffffffffu, ss, o);
    }
    __shared__ float sm[8], sm2[8];
    int w = tid >> 5, lane = tid & 31;
    if (lane == 0) { sm[w] = s; sm2[w] = ss; }
    __syncthreads();
    s = 0.f; ss = 0.f;
    #pragma unroll
    for (int i = 0; i < 8; i++) { s += sm[i]; ss += sm2[i]; }
    float mean = s * (1.0f / CDIM);
    float var = ss * (1.0f / CDIM) - mean * mean;
    float rstd = rsqrtf(var + 1e-5f);
    float4 gv = ((const float4*)g)[tid];
    float4 bv = ((const float4*)b)[tid];
    float o0 = (v.x - mean) * rstd * gv.x + bv.x;
    float o1 = (v.y - mean) * rstd * gv.y + bv.y;
    float o2 = (v.z - mean) * rstd * gv.z + bv.z;
    float o3 = (v.w - mean) * rstd * gv.w + bv.w;
    ushort4 hv, lv;
    bsplit(o0, hv.x, lv.x); bsplit(o1, hv.y, lv.y);
    bsplit(o2, hv.z, lv.z); bsplit(o3, hv.w, lv.w);
    *(ushort4*)(oh + (size_t)row * CDIM + tid * 4) = hv;
    *(ushort4*)(ol + (size_t)row * CDIM + tid * 4) = lv;
}

// ---------------- HMMA GEMM: D[M,N] = A[M,K] * B[N,K]^T ----------------
// A,B bf16 hi/lo split. BM=BN=128, BK=32, 8 warps (2m x 4n), warp tile 64x32.
// smem rows padded to 80 B (32 bf16 + 16 B) -> conflict-free ldmatrix.
#define RS 80
#define ARR_BYTES (128 * RS)              // 10240
#define STAGE_BYTES (4 * ARR_BYTES)       // 40960 (Ah, Al, Bh, Bl)
#define SMEM_GEMM (2 * STAGE_BYTES)       // 81920

__device__ __forceinline__ void gemm_load_stage(
    const unsigned short* __restrict__ Ah, const unsigned short* __restrict__ Al,
    const unsigned short* __restrict__ Bh, const unsigned short* __restrict__ Bl,
    int K, int m0, int n0, int k0, uint32_t smbase, int buf, int tid) {
    uint32_t sb = smbase + buf * STAGE_BYTES;
    #pragma unroll
    for (int it = 0; it < 8; it++) {
        int e = tid + it * 256;          // 0..2047
        int arr = e >> 9;                // 0..3
        int idx = e & 511;
        int row = idx >> 2;              // 0..127
        int ch = idx & 3;                // 16B chunk within 64B row
        const unsigned short* src = arr == 0 ? Ah : arr == 1 ? Al : arr == 2 ? Bh : Bl;
        int r0 = (arr < 2) ? m0 : n0;
        const unsigned short* g = src + (size_t)(r0 + row) * K + k0 + ch * 8;
        uint32_t d = sb + arr * ARR_BYTES + row * RS + ch * 16;
        CP_ASYNC16(d, g);
    }
}

__global__ __launch_bounds__(256)
void tgemm_kernel(const unsigned short* __restrict__ Ah, const unsigned short* __restrict__ Al,
                  const unsigned short* __restrict__ Bh, const unsigned short* __restrict__ Bl,
                  int K,
                  float* __restrict__ Cf, unsigned short* __restrict__ Ch,
                  unsigned short* __restrict__ Cl,
                  const float* __restrict__ bias, const float* __restrict__ res,
                  int relu, int ldc) {
    extern __shared__ char smem[];
    uint32_t smbase = cvta_s(smem);
    int tid = threadIdx.x;
    int m0 = blockIdx.x * 128, n0 = blockIdx.y * 128;
    int warp = tid >> 5, lane = tid & 31;
    int wm = (warp >> 2) * 64;           // warp m offset within tile
    int wn = (warp & 3) * 32;            // warp n offset
    int arow = lane & 15;
    uint32_t asel = (uint32_t)(lane >> 4) << 4;   // 0 or 16 bytes (k+8)
    int ln16 = lane & 15;
    int brow = ln16 & 7;
    uint32_t bsel = (uint32_t)((ln16 >> 3) & 1) << 4;

    float acc[4][4][4];
    #pragma unroll
    for (int i = 0; i < 4; i++)
        #pragma unroll
        for (int j = 0; j < 4; j++)
            #pragma unroll
            for (int q = 0; q < 4; q++) acc[i][j][q] = 0.f;

    int NS = K >> 5;                     // BK=32
    gemm_load_stage(Ah, Al, Bh, Bl, K, m0, n0, 0, smbase, 0, tid);
    CP_COMMIT();
    if (NS > 1) {
        gemm_load_stage(Ah, Al, Bh, Bl, K, m0, n0, 32, smbase, 1, tid);
        CP_COMMIT();
    }

    for (int s = 0; s < NS; s++) {
        if (s + 1 < NS) { CP_WAIT(1); } else { CP_WAIT(0); }
        __syncthreads();
        int buf = s & 1;
        uint32_t sA = smbase + buf * STAGE_BYTES;
        uint32_t sB = sA + 2 * ARR_BYTES;
        #pragma unroll
        for (int kk = 0; kk < 2; kk++) {
            uint32_t kb = kk * 32;       // 16 elems * 2B
            uint32_t ahf[4][4], alf[4][4], bhf[4][2], blf[4][2];
            #pragma unroll
            for (int i = 0; i < 4; i++) {
                uint32_t ra = sA + (uint32_t)(wm + i * 16 + arow) * RS + kb + asel;
                ldm_x4(ahf[i], ra);
                ldm_x4(alf[i], ra + ARR_BYTES);
            }
            #pragma unroll
            for (int j = 0; j < 4; j++) {
                uint32_t rb = sB + (uint32_t)(wn + j * 8 + brow) * RS + kb + bsel;
                ldm_x2(bhf[j], rb);
                ldm_x2(blf[j], rb + ARR_BYTES);
            }
            #pragma unroll
            for (int i = 0; i < 4; i++)
                #pragma unroll
                for (int j = 0; j < 4; j++) {
                    mma_bf16(acc[i][j], ahf[i], bhf[j]);
                    mma_bf16(acc[i][j], ahf[i], blf[j]);
                    mma_bf16(acc[i][j], alf[i], bhf[j]);
                }
        }
        __syncthreads();
        if (s + 2 < NS) {
            gemm_load_stage(Ah, Al, Bh, Bl, K, m0, n0, (s + 2) << 5, smbase, buf, tid);
            CP_COMMIT();
        }
    }

    // epilogue: d frag -> thread holds (qr, qc), (qr, qc+1), (qr+8, qc), (qr+8, qc+1)
    int qr = lane >> 2;
    int qc = (lane & 3) * 2;
    #pragma unroll
    for (int i = 0; i < 4; i++) {
        #pragma unroll
        for (int j = 0; j < 4; j++) {
            int col = n0 + wn + j * 8 + qc;
            #pragma unroll
            for (int half = 0; half < 2; half++) {
                int row = m0 + wm + i * 16 + qr + half * 8;
                float v0 = acc[i][j][half * 2 + 0];
                float v1 = acc[i][j][half * 2 + 1];
                if (bias) {
                    float2 bv = *(const float2*)(bias + col);
                    v0 += bv.x; v1 += bv.y;
                }
                size_t base = (size_t)row * ldc + col;
                if (res) {
                    float2 e = *(const float2*)(res + base);
                    v0 += e.x; v1 += e.y;
                }
                if (relu) { v0 = fmaxf(v0, 0.f); v1 = fmaxf(v1, 0.f); }
                if (Cf) { float2 o = {v0, v1}; *(float2*)(Cf + base) = o; }
                if (Ch) {
                    ushort2 hv, lv;
                    bsplit(v0, hv.x, lv.x);
                    bsplit(v1, hv.y, lv.y);
                    *(ushort2*)(Ch + base) = hv;
                    *(ushort2*)(Cl + base) = lv;
                }
            }
        }
    }
}

// ---------------- attention (fp32) ----------------
__global__ __launch_bounds__(256)
void qk_kernel(const float* __restrict__ qkv, float* __restrict__ scores) {
    int st = blockIdx.x, tt = blockIdx.y;
    if (st > tt) return;
    int bh = blockIdx.z;
    int b = bh >> 4, h = bh & 15;
    const float* Qb = qkv + (size_t)b * TLEN * (3 * CDIM) + h * HDIM;
    const float* Kb = Qb + CDIM;
    float* S = scores + (size_t)bh * TLEN * TLEN;
    __shared__ float Qs[64][64];
    __shared__ float Ks[64][64];
    int tid = threadIdx.x;
    int r = tid >> 2, cg = tid & 3;
    int t0 = tt * 64, s0 = st * 64;
    #pragma unroll
    for (int i = 0; i < 4; i++) {
        int c4 = cg + i * 4;
        float4 qv = *(const float4*)(Qb + (size_t)(t0 + r) * (3 * CDIM) + c4 * 4);
        Qs[c4 * 4 + 0][r] = qv.x; Qs[c4 * 4 + 1][r] = qv.y;
        Qs[c4 * 4 + 2][r] = qv.z; Qs[c4 * 4 + 3][r] = qv.w;
        float4 kv = *(const float4*)(Kb + (size_t)(s0 + r) * (3 * CDIM) + c4 * 4);
        Ks[c4 * 4 + 0][r] = kv.x; Ks[c4 * 4 + 1][r] = kv.y;
        Ks[c4 * 4 + 2][r] = kv.z; Ks[c4 * 4 + 3][r] = kv.w;
    }
    __syncthreads();
    int trow = tid >> 4, tcol = tid & 15;
    float acc[4][4];
    #pragma unroll
    for (int i = 0; i < 4; i++)
        #pragma unroll
        for (int j = 0; j < 4; j++) acc[i][j] = 0.f;
    #pragma unroll 8
    for (int d = 0; d < 64; d++) {
        float4 a = *(const float4*)&Qs[d][trow * 4];
        float4 bb = *(const float4*)&Ks[d][tcol * 4];
        float ar[4] = {a.x, a.y, a.z, a.w};
        float br[4] = {bb.x, bb.y, bb.z, bb.w};
        #pragma unroll
        for (int i = 0; i < 4; i++)
            #pragma unroll
            for (int j = 0; j < 4; j++) acc[i][j] = fmaf(ar[i], br[j], acc[i][j]);
    }
    #pragma unroll
    for (int i = 0; i < 4; i++) {
        float4 s4 = {acc[i][0] * 0.125f, acc[i][1] * 0.125f, acc[i][2] * 0.125f, acc[i][3] * 0.125f};
        *(float4*)(S + (size_t)(t0 + trow * 4 + i) * TLEN + s0 + tcol * 4) = s4;
    }
}

__global__ void softmax_kernel(float* __restrict__ scores) {
    int warp = threadIdx.x >> 5, lane = threadIdx.x & 31;
    size_t row = (size_t)blockIdx.x * 4 + warp;
    int t = (int)(row & (TLEN - 1));
    float* S = scores + row * TLEN;
    float m = -1e30f, l = 0.f;
    for (int s = lane; s <= t; s += 32) {
        float v = S[s];
        float nm = fmaxf(m, v);
        l = l * __expf(m - nm) + __expf(v - nm);
        m = nm;
    }
    #pragma unroll
    for (int o = 16; o > 0; o >>= 1) {
        float m2 = __shfl_xor_sync(0xffffffffu, m, o);
        float l2 = __shfl_xor_sync(0xffffffffu, l, o);
        float nm = fmaxf(m, m2);
        l = l * __expf(m - nm) + l2 * __expf(m2 - nm);
        m = nm;
    }
    float inv = 1.f / l;
    for (int s = lane; s < TLEN; s += 32)
        S[s] = (s <= t) ? __expf(S[s] - m) * inv : 0.f;
}

__global__ __launch_bounds__(256)
void av_kernel(const float* __restrict__ scores, const float* __restrict__ qkv,
               unsigned short* __restrict__ oh, unsigned short* __restrict__ ol) {
    int tt = blockIdx.x;
    int bh = blockIdx.y;
    int b = bh >> 4, h = bh & 15;
    const float* P = scores + (size_t)bh * TLEN * TLEN + (size_t)tt * 64 * TLEN;
    const float* V = qkv + (size_t)b * TLEN * (3 * CDIM) + 2 * CDIM + h * HDIM;
    int tid = threadIdx.x;
    __shared__ float Ps[64][64];
    __shared__ float Vs[64][64];
    int r = tid >> 2, cg = tid & 3;
    int trow = tid >> 4, tcol = tid & 15;
    float acc[4][4];
    #pragma unroll
    for (int i = 0; i < 4; i++)
        #pragma unroll
        for (int j = 0; j < 4; j++) acc[i][j] = 0.f;
    int nk = (tt + 1) * 64;
    for (int s0 = 0; s0 < nk; s0 += 64) {
        #pragma unroll
        for (int i = 0; i < 4; i++) {
            int c4 = cg + i * 4;
            float4 pv = *(const float4*)(P + (size_t)r * TLEN + s0 + c4 * 4);
            Ps[c4 * 4 + 0][r] = pv.x; Ps[c4 * 4 + 1][r] = pv.y;
            Ps[c4 * 4 + 2][r] = pv.z; Ps[c4 * 4 + 3][r] = pv.w;
            *(float4*)&Vs[r][c4 * 4] = *(const float4*)(V + (size_t)(s0 + r) * (3 * CDIM) + c4 * 4);
        }
        __syncthreads();
        #pragma unroll 8
        for (int s = 0; s < 64; s++) {
            float4 a = *(const float4*)&Ps[s][trow * 4];
            float4 bb = *(const float4*)&Vs[s][tcol * 4];
            float ar[4] = {a.x, a.y, a.z, a.w};
            float br[4] = {bb.x, bb.y, bb.z, bb.w};
            #pragma unroll
            for (int i = 0; i < 4; i++)
                #pragma unroll
                for (int j = 0; j < 4; j++) acc[i][j] = fmaf(ar[i], br[j], acc[i][j]);
        }
        __syncthreads();
    }
    int t0 = tt * 64;
    #pragma unroll
    for (int i = 0; i < 4; i++) {
        size_t base = (size_t)(b * TLEN + t0 + trow * 4 + i) * CDIM + h * HDIM + tcol * 4;
        ushort4 hv, lv;
        bsplit(acc[i][0], hv.x, lv.x); bsplit(acc[i][1], hv.y, lv.y);
        bsplit(acc[i][2], hv.z, lv.z); bsplit(acc[i][3], hv.w, lv.w);
        *(ushort4*)(oh + base) = hv;
        *(ushort4*)(ol + base) = lv;
    }
}

// ---------------- host ----------------
extern "C" void kernel_launch(void* const* d_in, const int* in_sizes, int n_in,
                              void* d_out, int out_size) {
    const int* idx = (const int*)d_in[0];
    const float* tok = (const float*)d_in[1];
    const float* pos = (const float*)d_in[2];
    const float* wq = (const float*)d_in[3];
    const float* wk = (const float*)d_in[4];
    const float* wv = (const float*)d_in[5];
    const float* wproj = (const float*)d_in[6];
    const float* bproj = (const float*)d_in[7];
    const float* ln1g = (const float*)d_in[8];
    const float* ln1b = (const float*)d_in[9];
    const float* ln2g = (const float*)d_in[10];
    const float* ln2b = (const float*)d_in[11];
    const float* w1 = (const float*)d_in[12];
    const float* b1 = (const float*)d_in[13];
    const float* w2 = (const float*)d_in[14];
    const float* b2 = (const float*)d_in[15];
    const float* lnfg = (const float*)d_in[16];
    const float* lnfb = (const float*)d_in[17];
    const float* wlm = (const float*)d_in[18];
    const float* blm = (const float*)d_in[19];
    float* out = (float*)d_out;

    float *px, *pqkv, *psc;
    unsigned short *phb_h, *phb_l, *pob_h, *pob_l, *pffb_h, *pffb_l;
    unsigned short *pwqkv_h, *pwqkv_l, *pwproj_h, *pwproj_l;
    unsigned short *pw1_h, *pw1_l, *pw2_h, *pw2_l, *pwlm_h, *pwlm_l;
    cudaGetSymbolAddress((void**)&px, g_x);
    cudaGetSymbolAddress((void**)&pqkv, g_qkv);
    cudaGetSymbolAddress((void**)&psc, g_scores);
    cudaGetSymbolAddress((void**)&phb_h, g_hb_h);
    cudaGetSymbolAddress((void**)&phb_l, g_hb_l);
    cudaGetSymbolAddress((void**)&pob_h, g_ob_h);
    cudaGetSymbolAddress((void**)&pob_l, g_ob_l);
    cudaGetSymbolAddress((void**)&pffb_h, g_ffb_h);
    cudaGetSymbolAddress((void**)&pffb_l, g_ffb_l);
    cudaGetSymbolAddress((void**)&pwqkv_h, g_wqkv_h);
    cudaGetSymbolAddress((void**)&pwqkv_l, g_wqkv_l);
    cudaGetSymbolAddress((void**)&pwproj_h, g_wproj_h);
    cudaGetSymbolAddress((void**)&pwproj_l, g_wproj_l);
    cudaGetSymbolAddress((void**)&pw1_h, g_w1_h);
    cudaGetSymbolAddress((void**)&pw1_l, g_w1_l);
    cudaGetSymbolAddress((void**)&pw2_h, g_w2_h);
    cudaGetSymbolAddress((void**)&pw2_l, g_w2_l);
    cudaGetSymbolAddress((void**)&pwlm_h, g_wlm_h);
    cudaGetSymbolAddress((void**)&pwlm_l, g_wlm_l);

    cudaFuncSetAttribute(tgemm_kernel, cudaFuncAttributeMaxDynamicSharedMemorySize, SMEM_GEMM);

    dim3 tb(32, 8);
    tsplit_qkv_kernel<<<dim3(96, 32, 8), tb>>>(wq, wk, wv, pwqkv_h, pwqkv_l);
    tsplit_mat_kernel<<<dim3(32, 32, 8), tb>>>(wproj, pwproj_h, pwproj_l, CDIM, CDIM);
    tsplit_mat_kernel<<<dim3(128, 32, 8), tb>>>(w1, pw1_h, pw1_l, CDIM, FF);
    tsplit_mat_kernel<<<dim3(32, 128, 8), tb>>>(w2, pw2_h, pw2_l, FF, CDIM);
    tsplit_mat_kernel<<<dim3(1000, 32, 1), tb>>>(wlm, pwlm_h, pwlm_l, CDIM, VOCAB);

    embed_kernel<<<NTOK, 256>>>(idx, tok, pos, px);

    for (int l = 0; l < NLAYER; l++) {
        ln_kernel<<<NTOK, 256>>>(px, ln1g + (size_t)l * CDIM, ln1b + (size_t)l * CDIM, phb_h, phb_l);
        tgemm_kernel<<<dim3(32, 24), 256, SMEM_GEMM>>>(
            phb_h, phb_l, pwqkv_h + (size_t)l * 3072 * 1024, pwqkv_l + (size_t)l * 3072 * 1024,
            CDIM, pqkv, nullptr, nullptr, nullptr, nullptr, 0, 3 * CDIM);
        qk_kernel<<<dim3(16, 16, BATCH * NHEAD), 256>>>(pqkv, psc);
        softmax_kernel<<<BATCH * NHEAD * TLEN / 4, 128>>>(psc);
        av_kernel<<<dim3(16, BATCH * NHEAD), 256>>>(psc, pqkv, pob_h, pob_l);
        tgemm_kernel<<<dim3(32, 8), 256, SMEM_GEMM>>>(
            pob_h, pob_l, pwproj_h + (size_t)l * CDIM * CDIM, pwproj_l + (size_t)l * CDIM * CDIM,
            CDIM, px, nullptr, nullptr, bproj + (size_t)l * CDIM, px, 0, CDIM);
        ln_kernel<<<NTOK, 256>>>(px, ln2g + (size_t)l * CDIM, ln2b + (size_t)l * CDIM, phb_h, phb_l);
        tgemm_kernel<<<dim3(32, 32), 256, SMEM_GEMM>>>(
            phb_h, phb_l, pw1_h + (size_t)l * FF * CDIM, pw1_l + (size_t)l * FF * CDIM,
            CDIM, nullptr, pffb_h, pffb_l, b1 + (size_t)l * FF, nullptr, 1, FF);
        tgemm_kernel<<<dim3(32, 8), 256, SMEM_GEMM>>>(
            pffb_h, pffb_l, pw2_h + (size_t)l * CDIM * FF, pw2_l + (size_t)l * CDIM * FF,
            FF, px, nullptr, nullptr, b2 + (size_t)l * CDIM, px, 0, CDIM);
    }
    ln_kernel<<<NTOK, 256>>>(px, lnfg, lnfb, phb_h, phb_l);
    tgemm_kernel<<<dim3(32, 250), 256, SMEM_GEMM>>>(
        phb_h, phb_l, pwlm_h, pwlm_l, CDIM, out, nullptr, nullptr, blm, nullptr, 0, VOCAB);
}

// round 5
// speedup vs baseline: 3.4931x; 1.1930x over previous
#include <cuda_runtime.h>
#include <cuda_bf16.h>
#include <cstdint>
#include <math.h>

#define BATCH 4
#define TLEN 1024
#define CDIM 1024
#define NHEAD 16
#define HDIM 64
#define NLAYER 8
#define VOCAB 32000
#define NTOK (BATCH * TLEN)
#define FF (4 * CDIM)

// ---------------- device scratch ----------------
__device__ float g_x[NTOK * CDIM];
__device__ unsigned short g_qkvb_h[NTOK * 3 * CDIM], g_qkvb_l[NTOK * 3 * CDIM];
__device__ unsigned short g_hb_h[NTOK * CDIM], g_hb_l[NTOK * CDIM];
__device__ unsigned short g_ob_h[NTOK * CDIM], g_ob_l[NTOK * CDIM];
__device__ unsigned short g_ffb_h[(size_t)NTOK * FF], g_ffb_l[(size_t)NTOK * FF];
__device__ unsigned short g_wqkv_h[(size_t)NLAYER * 3 * CDIM * CDIM], g_wqkv_l[(size_t)NLAYER * 3 * CDIM * CDIM];
__device__ unsigned short g_wproj_h[(size_t)NLAYER * CDIM * CDIM], g_wproj_l[(size_t)NLAYER * CDIM * CDIM];
__device__ unsigned short g_w1_h[(size_t)NLAYER * FF * CDIM], g_w1_l[(size_t)NLAYER * FF * CDIM];
__device__ unsigned short g_w2_h[(size_t)NLAYER * CDIM * FF], g_w2_l[(size_t)NLAYER * CDIM * FF];
__device__ unsigned short g_wlm_h[(size_t)VOCAB * CDIM], g_wlm_l[(size_t)VOCAB * CDIM];

// ---------------- helpers ----------------
__device__ __forceinline__ uint32_t cvta_s(const void* p) {
    uint32_t a;
    asm("{ .reg .u64 t; cvta.to.shared.u64 t, %1; cvt.u32.u64 %0, t; }" : "=r"(a) : "l"(p));
    return a;
}
#define CP_ASYNC16(dst, src) \
    asm volatile("cp.async.cg.shared.global [%0], [%1], 16;" :: "r"(dst), "l"(src))
#define CP_COMMIT() asm volatile("cp.async.commit_group;" ::: "memory")
#define CP_WAIT(n)  asm volatile("cp.async.wait_group %0;" :: "n"(n) : "memory")

__device__ __forceinline__ void ldm_x4(uint32_t* r, uint32_t addr) {
    asm volatile("ldmatrix.sync.aligned.m8n8.x4.shared.b16 {%0,%1,%2,%3}, [%4];"
                 : "=r"(r[0]), "=r"(r[1]), "=r"(r[2]), "=r"(r[3]) : "r"(addr));
}
__device__ __forceinline__ void ldm_x2(uint32_t* r, uint32_t addr) {
    asm volatile("ldmatrix.sync.aligned.m8n8.x2.shared.b16 {%0,%1}, [%2];"
                 : "=r"(r[0]), "=r"(r[1]) : "r"(addr));
}
__device__ __forceinline__ void ldm_x2t(uint32_t* r, uint32_t addr) {
    asm volatile("ldmatrix.sync.aligned.m8n8.x2.trans.shared.b16 {%0,%1}, [%2];"
                 : "=r"(r[0]), "=r"(r[1]) : "r"(addr));
}
__device__ __forceinline__ void mma_bf16(float* d, const uint32_t* a, const uint32_t* b) {
    asm volatile(
        "mma.sync.aligned.m16n8k16.row.col.f32.bf16.bf16.f32 "
        "{%0,%1,%2,%3}, {%4,%5,%6,%7}, {%8,%9}, {%0,%1,%2,%3};"
        : "+f"(d[0]), "+f"(d[1]), "+f"(d[2]), "+f"(d[3])
        : "r"(a[0]), "r"(a[1]), "r"(a[2]), "r"(a[3]), "r"(b[0]), "r"(b[1]));
}
__device__ __forceinline__ void bsplit(float v, unsigned short& h, unsigned short& l) {
    __nv_bfloat16 hb = __float2bfloat16(v);
    __nv_bfloat16 lb = __float2bfloat16(v - __bfloat162float(hb));
    h = __bfloat16_as_ushort(hb);
    l = __bfloat16_as_ushort(lb);
}
__device__ __forceinline__ void pack2(float a, float b, uint32_t& hi, uint32_t& lo) {
    unsigned short h0, l0, h1, l1;
    bsplit(a, h0, l0);
    bsplit(b, h1, l1);
    hi = (uint32_t)h0 | ((uint32_t)h1 << 16);
    lo = (uint32_t)l0 | ((uint32_t)l1 << 16);
}

// ---------------- weight prep (transpose + hi/lo split) ----------------
__global__ void tsplit_qkv_kernel(const float* __restrict__ wq, const float* __restrict__ wk,
                                  const float* __restrict__ wv,
                                  unsigned short* __restrict__ dh, unsigned short* __restrict__ dl) {
    __shared__ float t[32][33];
    int n0 = blockIdx.x * 32, k0 = blockIdx.y * 32, l = blockIdx.z;
    int sel = n0 >> 10;
    const float* src = sel == 0 ? wq : (sel == 1 ? wk : wv);
    int within = n0 & 1023;
    int h = within >> 6, d0 = within & 63;
    const float* sp = src + ((size_t)(l * 16 + h) * 1024 + k0) * 64 + d0;
    int tx = threadIdx.x, ty = threadIdx.y;
    #pragma unroll
    for (int i = 0; i < 4; i++) t[ty + i * 8][tx] = sp[(size_t)(ty + i * 8) * 64 + tx];
    __syncthreads();
    size_t ob = (size_t)l * 3072 * 1024;
    #pragma unroll
    for (int i = 0; i < 4; i++) {
        int n = n0 + ty + i * 8, k = k0 + tx;
        unsigned short hh, ll;
        bsplit(t[tx][ty + i * 8], hh, ll);
        dh[ob + (size_t)n * 1024 + k] = hh;
        dl[ob + (size_t)n * 1024 + k] = ll;
    }
}
__global__ void tsplit_mat_kernel(const float* __restrict__ src,
                                  unsigned short* __restrict__ dh, unsigned short* __restrict__ dl,
                                  int K, int N) {
    __shared__ float t[32][33];
    int n0 = blockIdx.x * 32, k0 = blockIdx.y * 32;
    size_t l = blockIdx.z;
    const float* sp = src + l * (size_t)K * N;
    int tx = threadIdx.x, ty = threadIdx.y;
    #pragma unroll
    for (int i = 0; i < 4; i++) t[ty + i * 8][tx] = sp[(size_t)(k0 + ty + i * 8) * N + n0 + tx];
    __syncthreads();
    size_t ob = l * (size_t)K * N;
    #pragma unroll
    for (int i = 0; i < 4; i++) {
        int n = n0 + ty + i * 8, k = k0 + tx;
        unsigned short hh, ll;
        bsplit(t[tx][ty + i * 8], hh, ll);
        dh[ob + (size_t)n * K + k] = hh;
        dl[ob + (size_t)n * K + k] = ll;
    }
}

// ---------------- embed ----------------
__global__ void embed_kernel(const int* __restrict__ idx, const float* __restrict__ tok,
                             const float* __restrict__ pos, float* __restrict__ x) {
    int row = blockIdx.x;
    int t = row & (TLEN - 1);
    int token = idx[row];
    const float4* te = (const float4*)(tok + (size_t)token * CDIM);
    const float4* pe = (const float4*)(pos + (size_t)t * CDIM);
    float4* xo = (float4*)(x + (size_t)row * CDIM);
    int i = threadIdx.x;
    float4 a = te[i], b = pe[i];
    a.x += b.x; a.y += b.y; a.z += b.z; a.w += b.w;
    xo[i] = a;
}

// ---------------- LayerNorm -> bf16 hi/lo ----------------
__global__ void ln_kernel(const float* __restrict__ x, const float* __restrict__ g,
                          const float* __restrict__ b,
                          unsigned short* __restrict__ oh, unsigned short* __restrict__ ol) {
    int row = blockIdx.x;
    int tid = threadIdx.x;
    float4 v = ((const float4*)(x + (size_t)row * CDIM))[tid];
    float s = v.x + v.y + v.z + v.w;
    float ss = v.x * v.x + v.y * v.y + v.z * v.z + v.w * v.w;
    #pragma unroll
    for (int o = 16; o > 0; o >>= 1) {
        s += __shfl_xor_sync(0xffffffffu, s, o);
        ss += __shfl_xor_sync(0xffffffffu, ss, o);
    }
    __shared__ float sm[8], sm2[8];
    int w = tid >> 5, lane = tid & 31;
    if (lane == 0) { sm[w] = s; sm2[w] = ss; }
    __syncthreads();
    s = 0.f; ss = 0.f;
    #pragma unroll
    for (int i = 0; i < 8; i++) { s += sm[i]; ss += sm2[i]; }
    float mean = s * (1.0f / CDIM);
    float var = ss * (1.0f / CDIM) - mean * mean;
    float rstd = rsqrtf(var + 1e-5f);
    float4 gv = ((const float4*)g)[tid];
    float4 bv = ((const float4*)b)[tid];
    float o0 = (v.x - mean) * rstd * gv.x + bv.x;
    float o1 = (v.y - mean) * rstd * gv.y + bv.y;
    float o2 = (v.z - mean) * rstd * gv.z + bv.z;
    float o3 = (v.w - mean) * rstd * gv.w + bv.w;
    ushort4 hv, lv;
    bsplit(o0, hv.x, lv.x); bsplit(o1, hv.y, lv.y);
    bsplit(o2, hv.z, lv.z); bsplit(o3, hv.w, lv.w);
    *(ushort4*)(oh + (size_t)row * CDIM + tid * 4) = hv;
    *(ushort4*)(ol + (size_t)row * CDIM + tid * 4) = lv;
}

// ---------------- HMMA GEMM: D[M,N] = A[M,K] * B[N,K]^T ----------------
#define RS 80
#define ARR_BYTES (128 * RS)
#define STAGE_BYTES (4 * ARR_BYTES)
#define SMEM_GEMM (2 * STAGE_BYTES)

__device__ __forceinline__ void gemm_load_stage(
    const unsigned short* __restrict__ Ah, const unsigned short* __restrict__ Al,
    const unsigned short* __restrict__ Bh, const unsigned short* __restrict__ Bl,
    int K, int m0, int n0, int k0, uint32_t smbase, int buf, int tid) {
    uint32_t sb = smbase + buf * STAGE_BYTES;
    #pragma unroll
    for (int it = 0; it < 8; it++) {
        int e = tid + it * 256;
        int arr = e >> 9;
        int idx = e & 511;
        int row = idx >> 2;
        int ch = idx & 3;
        const unsigned short* src = arr == 0 ? Ah : arr == 1 ? Al : arr == 2 ? Bh : Bl;
        int r0 = (arr < 2) ? m0 : n0;
        const unsigned short* g = src + (size_t)(r0 + row) * K + k0 + ch * 8;
        uint32_t d = sb + arr * ARR_BYTES + row * RS + ch * 16;
        CP_ASYNC16(d, g);
    }
}

__global__ __launch_bounds__(256)
void tgemm_kernel(const unsigned short* __restrict__ Ah, const unsigned short* __restrict__ Al,
                  const unsigned short* __restrict__ Bh, const unsigned short* __restrict__ Bl,
                  int K,
                  float* __restrict__ Cf, unsigned short* __restrict__ Ch,
                  unsigned short* __restrict__ Cl,
                  const float* __restrict__ bias, const float* __restrict__ res,
                  int relu, int ldc) {
    extern __shared__ char smem[];
    uint32_t smbase = cvta_s(smem);
    int tid = threadIdx.x;
    int m0 = blockIdx.x * 128, n0 = blockIdx.y * 128;
    int warp = tid >> 5, lane = tid & 31;
    int wm = (warp >> 2) * 64;
    int wn = (warp & 3) * 32;
    int arow = lane & 15;
    uint32_t asel = (uint32_t)(lane >> 4) << 4;
    int ln16 = lane & 15;
    int brow = ln16 & 7;
    uint32_t bsel = (uint32_t)((ln16 >> 3) & 1) << 4;

    float acc[4][4][4];
    #pragma unroll
    for (int i = 0; i < 4; i++)
        #pragma unroll
        for (int j = 0; j < 4; j++)
            #pragma unroll
            for (int q = 0; q < 4; q++) acc[i][j][q] = 0.f;

    int NS = K >> 5;
    gemm_load_stage(Ah, Al, Bh, Bl, K, m0, n0, 0, smbase, 0, tid);
    CP_COMMIT();
    if (NS > 1) {
        gemm_load_stage(Ah, Al, Bh, Bl, K, m0, n0, 32, smbase, 1, tid);
        CP_COMMIT();
    }

    for (int s = 0; s < NS; s++) {
        if (s + 1 < NS) { CP_WAIT(1); } else { CP_WAIT(0); }
        __syncthreads();
        int buf = s & 1;
        uint32_t sA = smbase + buf * STAGE_BYTES;
        uint32_t sB = sA + 2 * ARR_BYTES;
        #pragma unroll
        for (int kk = 0; kk < 2; kk++) {
            uint32_t kb = kk * 32;
            uint32_t ahf[4][4], alf[4][4], bhf[4][2], blf[4][2];
            #pragma unroll
            for (int i = 0; i < 4; i++) {
                uint32_t ra = sA + (uint32_t)(wm + i * 16 + arow) * RS + kb + asel;
                ldm_x4(ahf[i], ra);
                ldm_x4(alf[i], ra + ARR_BYTES);
            }
            #pragma unroll
            for (int j = 0; j < 4; j++) {
                uint32_t rb = sB + (uint32_t)(wn + j * 8 + brow) * RS + kb + bsel;
                ldm_x2(bhf[j], rb);
                ldm_x2(blf[j], rb + ARR_BYTES);
            }
            #pragma unroll
            for (int i = 0; i < 4; i++)
                #pragma unroll
                for (int j = 0; j < 4; j++) {
                    mma_bf16(acc[i][j], ahf[i], bhf[j]);
                    mma_bf16(acc[i][j], ahf[i], blf[j]);
                    mma_bf16(acc[i][j], alf[i], bhf[j]);
                }
        }
        __syncthreads();
        if (s + 2 < NS) {
            gemm_load_stage(Ah, Al, Bh, Bl, K, m0, n0, (s + 2) << 5, smbase, buf, tid);
            CP_COMMIT();
        }
    }

    int qr = lane >> 2;
    int qc = (lane & 3) * 2;
    #pragma unroll
    for (int i = 0; i < 4; i++) {
        #pragma unroll
        for (int j = 0; j < 4; j++) {
            int col = n0 + wn + j * 8 + qc;
            #pragma unroll
            for (int half = 0; half < 2; half++) {
                int row = m0 + wm + i * 16 + qr + half * 8;
                float v0 = acc[i][j][half * 2 + 0];
                float v1 = acc[i][j][half * 2 + 1];
                if (bias) {
                    float2 bv = *(const float2*)(bias + col);
                    v0 += bv.x; v1 += bv.y;
                }
                size_t base = (size_t)row * ldc + col;
                if (res) {
                    float2 e = *(const float2*)(res + base);
                    v0 += e.x; v1 += e.y;
                }
                if (relu) { v0 = fmaxf(v0, 0.f); v1 = fmaxf(v1, 0.f); }
                if (Cf) { float2 o = {v0, v1}; *(float2*)(Cf + base) = o; }
                if (Ch) {
                    ushort2 hv, lv;
                    bsplit(v0, hv.x, lv.x);
                    bsplit(v1, hv.y, lv.y);
                    *(ushort2*)(Ch + base) = hv;
                    *(ushort2*)(Cl + base) = lv;
                }
            }
        }
    }
}

// ---------------- fused flash attention ----------------
// One CTA = one (bh, 64-row t-tile). 128 threads (4 warps, 16 rows each).
// Q/K/V bf16 hi/lo from fused qkv buffer. Online softmax in fp32 regs.
#define FRS 144
#define FARR (64 * FRS)                 // 9216
#define FKV_STAGE (4 * FARR)            // 36864
#define SMEM_FLASH (2 * FARR + 2 * FKV_STAGE)  // 92160

__device__ __forceinline__ void flash_load_q(
    const unsigned short* __restrict__ qh, const unsigned short* __restrict__ ql,
    int rowbase, int colbase, uint32_t smbase, int tid) {
    #pragma unroll
    for (int it = 0; it < 8; it++) {
        int e = tid + it * 128;
        int arr = e >> 9;
        int idx = e & 511;
        int row = idx >> 3, ch = idx & 7;
        const unsigned short* src = arr == 0 ? qh : ql;
        const unsigned short* g = src + (size_t)(rowbase + row) * (3 * CDIM) + colbase + ch * 8;
        CP_ASYNC16(smbase + arr * FARR + row * FRS + ch * 16, g);
    }
}
__device__ __forceinline__ void flash_load_kv(
    const unsigned short* __restrict__ qh, const unsigned short* __restrict__ ql,
    int rowbase, int kcol, int vcol, uint32_t sb, int tid) {
    #pragma unroll
    for (int it = 0; it < 16; it++) {
        int e = tid + it * 128;
        int arr = e >> 9;                // 0=Kh 1=Kl 2=Vh 3=Vl
        int idx = e & 511;
        int row = idx >> 3, ch = idx & 7;
        const unsigned short* src = (arr & 1) ? ql : qh;
        int col = (arr < 2) ? kcol : vcol;
        const unsigned short* g = src + (size_t)(rowbase + row) * (3 * CDIM) + col + ch * 8;
        CP_ASYNC16(sb + arr * FARR + row * FRS + ch * 16, g);
    }
}

__global__ __launch_bounds__(128)
void flash_kernel(const unsigned short* __restrict__ qh, const unsigned short* __restrict__ ql,
                  unsigned short* __restrict__ oh, unsigned short* __restrict__ ol) {
    extern __shared__ char smem[];
    uint32_t smbase = cvta_s(smem);
    int tid = threadIdx.x;
    int tt = blockIdx.x;                 // t-tile 0..15
    int bh = blockIdx.y;
    int b = bh >> 4, h = bh & 15;
    int t0 = tt * 64;
    int qrowbase = b * TLEN + t0;
    int qcol = h * HDIM;
    int kcol = CDIM + h * HDIM;
    int vcol = 2 * CDIM + h * HDIM;

    int warp = tid >> 5, lane = tid & 31;
    int wm = warp * 16;
    int arow = lane & 15;
    uint32_t asel = (uint32_t)(lane >> 4) << 4;
    int ln16 = lane & 15;
    int brow = ln16 & 7;
    uint32_t bsel = (uint32_t)((ln16 >> 3) & 1) << 4;
    int qr = lane >> 2;
    int qc = (lane & 3) * 2;

    float O[8][4];
    #pragma unroll
    for (int j = 0; j < 8; j++)
        #pragma unroll
        for (int q = 0; q < 4; q++) O[j][q] = 0.f;
    float m0r = -1e30f, m1r = -1e30f, l0 = 0.f, l1 = 0.f;

    int NS = tt + 1;
    uint32_t kvbase = smbase + 2 * FARR;

    flash_load_q(qh, ql, qrowbase, qcol, smbase, tid);
    flash_load_kv(qh, ql, b * TLEN, kcol, vcol, kvbase, tid);
    CP_COMMIT();
    if (NS > 1) {
        flash_load_kv(qh, ql, b * TLEN + 64, kcol, vcol, kvbase + FKV_STAGE, tid);
        CP_COMMIT();
    }

    for (int st = 0; st < NS; st++) {
        if (st + 1 < NS) { CP_WAIT(1); } else { CP_WAIT(0); }
        __syncthreads();
        uint32_t sKV = kvbase + (st & 1) * FKV_STAGE;
        uint32_t sK = sKV, sV = sKV + 2 * FARR;

        // ---- S = Q K^T (3-term) ----
        float S[8][4];
        #pragma unroll
        for (int j = 0; j < 8; j++)
            #pragma unroll
            for (int q = 0; q < 4; q++) S[j][q] = 0.f;
        #pragma unroll
        for (int d = 0; d < 4; d++) {
            uint32_t kb = d * 32;
            uint32_t ah[4], al[4];
            uint32_t ra = smbase + (uint32_t)(wm + arow) * FRS + kb + asel;
            ldm_x4(ah, ra);
            ldm_x4(al, ra + FARR);
            #pragma unroll
            for (int j = 0; j < 8; j++) {
                uint32_t bhf[2], blf[2];
                uint32_t rb = sK + (uint32_t)(j * 8 + brow) * FRS + kb + bsel;
                ldm_x2(bhf, rb);
                ldm_x2(blf, rb + FARR);
                mma_bf16(S[j], ah, bhf);
                mma_bf16(S[j], ah, blf);
                mma_bf16(S[j], al, bhf);
            }
        }
        // scale + causal mask (diagonal tile only)
        if (st == tt) {
            int r0 = wm + qr, r1 = wm + qr + 8;
            #pragma unroll
            for (int j = 0; j < 8; j++) {
                int c0 = j * 8 + qc;
                S[j][0] = (c0     > r0) ? -1e30f : S[j][0] * 0.125f;
                S[j][1] = (c0 + 1 > r0) ? -1e30f : S[j][1] * 0.125f;
                S[j][2] = (c0     > r1) ? -1e30f : S[j][2] * 0.125f;
                S[j][3] = (c0 + 1 > r1) ? -1e30f : S[j][3] * 0.125f;
            }
        } else {
            #pragma unroll
            for (int j = 0; j < 8; j++)
                #pragma unroll
                for (int q = 0; q < 4; q++) S[j][q] *= 0.125f;
        }
        // ---- online softmax ----
        float mx0 = -1e30f, mx1 = -1e30f;
        #pragma unroll
        for (int j = 0; j < 8; j++) {
            mx0 = fmaxf(mx0, fmaxf(S[j][0], S[j][1]));
            mx1 = fmaxf(mx1, fmaxf(S[j][2], S[j][3]));
        }
        mx0 = fmaxf(mx0, __shfl_xor_sync(0xffffffffu, mx0, 1));
        mx0 = fmaxf(mx0, __shfl_xor_sync(0xffffffffu, mx0, 2));
        mx1 = fmaxf(mx1, __shfl_xor_sync(0xffffffffu, mx1, 1));
        mx1 = fmaxf(mx1, __shfl_xor_sync(0xffffffffu, mx1, 2));
        float mn0 = fmaxf(m0r, mx0), mn1 = fmaxf(m1r, mx1);
        float c0 = __expf(m0r - mn0), c1 = __expf(m1r - mn1);
        float rs0 = 0.f, rs1 = 0.f;
        #pragma unroll
        for (int j = 0; j < 8; j++) {
            S[j][0] = __expf(S[j][0] - mn0);
            S[j][1] = __expf(S[j][1] - mn0);
            S[j][2] = __expf(S[j][2] - mn1);
            S[j][3] = __expf(S[j][3] - mn1);
            rs0 += S[j][0] + S[j][1];
            rs1 += S[j][2] + S[j][3];
        }
        rs0 += __shfl_xor_sync(0xffffffffu, rs0, 1);
        rs0 += __shfl_xor_sync(0xffffffffu, rs0, 2);
        rs1 += __shfl_xor_sync(0xffffffffu, rs1, 1);
        rs1 += __shfl_xor_sync(0xffffffffu, rs1, 2);
        l0 = l0 * c0 + rs0;
        l1 = l1 * c1 + rs1;
        m0r = mn0; m1r = mn1;
        #pragma unroll
        for (int j = 0; j < 8; j++) {
            O[j][0] *= c0; O[j][1] *= c0;
            O[j][2] *= c1; O[j][3] *= c1;
        }
        // ---- O += P V (3-term), P from S regs ----
        #pragma unroll
        for (int kk = 0; kk < 4; kk++) {
            int j0 = 2 * kk, j1 = 2 * kk + 1;
            uint32_t pah[4], pal[4];
            pack2(S[j0][0], S[j0][1], pah[0], pal[0]);
            pack2(S[j0][2], S[j0][3], pah[1], pal[1]);
            pack2(S[j1][0], S[j1][1], pah[2], pal[2]);
            pack2(S[j1][2], S[j1][3], pah[3], pal[3]);
            uint32_t vrow = (uint32_t)(kk * 16 + (ln16 & 7) + ((ln16 >> 3) & 1) * 8);
            #pragma unroll
            for (int jd = 0; jd < 8; jd++) {
                uint32_t vhf[2], vlf[2];
                uint32_t rv = sV + vrow * FRS + jd * 16;
                ldm_x2t(vhf, rv);
                ldm_x2t(vlf, rv + FARR);
                mma_bf16(O[jd], pah, vhf);
                mma_bf16(O[jd], pah, vlf);
                mma_bf16(O[jd], pal, vhf);
            }
        }
        __syncthreads();
        if (st + 2 < NS) {
            flash_load_kv(qh, ql, b * TLEN + (st + 2) * 64, kcol, vcol,
                          kvbase + (st & 1) * FKV_STAGE, tid);
            CP_COMMIT();
        }
    }

    float inv0 = 1.f / l0, inv1 = 1.f / l1;
    int row0 = b * TLEN + t0 + wm + qr;
    #pragma unroll
    for (int jd = 0; jd < 8; jd++) {
        int col = qcol + jd * 8 + qc;
        ushort2 hv, lv;
        bsplit(O[jd][0] * inv0, hv.x, lv.x);
        bsplit(O[jd][1] * inv0, hv.y, lv.y);
        *(ushort2*)(oh + (size_t)row0 * CDIM + col) = hv;
        *(ushort2*)(ol + (size_t)row0 * CDIM + col) = lv;
        bsplit(O[jd][2] * inv1, hv.x, lv.x);
        bsplit(O[jd][3] * inv1, hv.y, lv.y);
        *(ushort2*)(oh + (size_t)(row0 + 8) * CDIM + col) = hv;
        *(ushort2*)(ol + (size_t)(row0 + 8) * CDIM + col) = lv;
    }
}

// ---------------- host ----------------
extern "C" void kernel_launch(void* const* d_in, const int* in_sizes, int n_in,
                              void* d_out, int out_size) {
    const int* idx = (const int*)d_in[0];
    const float* tok = (const float*)d_in[1];
    const float* pos = (const float*)d_in[2];
    const float* wq = (const float*)d_in[3];
    const float* wk = (const float*)d_in[4];
    const float* wv = (const float*)d_in[5];
    const float* wproj = (const float*)d_in[6];
    const float* bproj = (const float*)d_in[7];
    const float* ln1g = (const float*)d_in[8];
    const float* ln1b = (const float*)d_in[9];
    const float* ln2g = (const float*)d_in[10];
    const float* ln2b = (const float*)d_in[11];
    const float* w1 = (const float*)d_in[12];
    const float* b1 = (const float*)d_in[13];
    const float* w2 = (const float*)d_in[14];
    const float* b2 = (const float*)d_in[15];
    const float* lnfg = (const float*)d_in[16];
    const float* lnfb = (const float*)d_in[17];
    const float* wlm = (const float*)d_in[18];
    const float* blm = (const float*)d_in[19];
    float* out = (float*)d_out;

    float* px;
    unsigned short *pqkvb_h, *pqkvb_l;
    unsigned short *phb_h, *phb_l, *pob_h, *pob_l, *pffb_h, *pffb_l;
    unsigned short *pwqkv_h, *pwqkv_l, *pwproj_h, *pwproj_l;
    unsigned short *pw1_h, *pw1_l, *pw2_h, *pw2_l, *pwlm_h, *pwlm_l;
    cudaGetSymbolAddress((void**)&px, g_x);
    cudaGetSymbolAddress((void**)&pqkvb_h, g_qkvb_h);
    cudaGetSymbolAddress((void**)&pqkvb_l, g_qkvb_l);
    cudaGetSymbolAddress((void**)&phb_h, g_hb_h);
    cudaGetSymbolAddress((void**)&phb_l, g_hb_l);
    cudaGetSymbolAddress((void**)&pob_h, g_ob_h);
    cudaGetSymbolAddress((void**)&pob_l, g_ob_l);
    cudaGetSymbolAddress((void**)&pffb_h, g_ffb_h);
    cudaGetSymbolAddress((void**)&pffb_l, g_ffb_l);
    cudaGetSymbolAddress((void**)&pwqkv_h, g_wqkv_h);
    cudaGetSymbolAddress((void**)&pwqkv_l, g_wqkv_l);
    cudaGetSymbolAddress((void**)&pwproj_h, g_wproj_h);
    cudaGetSymbolAddress((void**)&pwproj_l, g_wproj_l);
    cudaGetSymbolAddress((void**)&pw1_h, g_w1_h);
    cudaGetSymbolAddress((void**)&pw1_l, g_w1_l);
    cudaGetSymbolAddress((void**)&pw2_h, g_w2_h);
    cudaGetSymbolAddress((void**)&pw2_l, g_w2_l);
    cudaGetSymbolAddress((void**)&pwlm_h, g_wlm_h);
    cudaGetSymbolAddress((void**)&pwlm_l, g_wlm_l);

    cudaFuncSetAttribute(tgemm_kernel, cudaFuncAttributeMaxDynamicSharedMemorySize, SMEM_GEMM);
    cudaFuncSetAttribute(flash_kernel, cudaFuncAttributeMaxDynamicSharedMemorySize, SMEM_FLASH);

    dim3 tb(32, 8);
    tsplit_qkv_kernel<<<dim3(96, 32, 8), tb>>>(wq, wk, wv, pwqkv_h, pwqkv_l);
    tsplit_mat_kernel<<<dim3(32, 32, 8), tb>>>(wproj, pwproj_h, pwproj_l, CDIM, CDIM);
    tsplit_mat_kernel<<<dim3(128, 32, 8), tb>>>(w1, pw1_h, pw1_l, CDIM, FF);
    tsplit_mat_kernel<<<dim3(32, 128, 8), tb>>>(w2, pw2_h, pw2_l, FF, CDIM);
    tsplit_mat_kernel<<<dim3(1000, 32, 1), tb>>>(wlm, pwlm_h, pwlm_l, CDIM, VOCAB);

    embed_kernel<<<NTOK, 256>>>(idx, tok, pos, px);

    for (int l = 0; l < NLAYER; l++) {
        ln_kernel<<<NTOK, 256>>>(px, ln1g + (size_t)l * CDIM, ln1b + (size_t)l * CDIM, phb_h, phb_l);
        tgemm_kernel<<<dim3(32, 24), 256, SMEM_GEMM>>>(
            phb_h, phb_l, pwqkv_h + (size_t)l * 3072 * 1024, pwqkv_l + (size_t)l * 3072 * 1024,
            CDIM, nullptr, pqkvb_h, pqkvb_l, nullptr, nullptr, 0, 3 * CDIM);
        flash_kernel<<<dim3(16, BATCH * NHEAD), 128, SMEM_FLASH>>>(pqkvb_h, pqkvb_l, pob_h, pob_l);
        tgemm_kernel<<<dim3(32, 8), 256, SMEM_GEMM>>>(
            pob_h, pob_l, pwproj_h + (size_t)l * CDIM * CDIM, pwproj_l + (size_t)l * CDIM * CDIM,
            CDIM, px, nullptr, nullptr, bproj + (size_t)l * CDIM, px, 0, CDIM);
        ln_kernel<<<NTOK, 256>>>(px, ln2g + (size_t)l * CDIM, ln2b + (size_t)l * CDIM, phb_h, phb_l);
        tgemm_kernel<<<dim3(32, 32), 256, SMEM_GEMM>>>(
            phb_h, phb_l, pw1_h + (size_t)l * FF * CDIM, pw1_l + (size_t)l * FF * CDIM,
            CDIM, nullptr, pffb_h, pffb_l, b1 + (size_t)l * FF, nullptr, 1, FF);
        tgemm_kernel<<<dim3(32, 8), 256, SMEM_GEMM>>>(
            pffb_h, pffb_l, pw2_h + (size_t)l * CDIM * FF, pw2_l + (size_t)l * CDIM * FF,
            FF, px, nullptr, nullptr, b2 + (size_t)l * CDIM, px, 0, CDIM);
    }
    ln_kernel<<<NTOK, 256>>>(px, lnfg, lnfb, phb_h, phb_l);
    tgemm_kernel<<<dim3(32, 250), 256, SMEM_GEMM>>>(
        phb_h, phb_l, pwlm_h, pwlm_l, CDIM, out, nullptr, nullptr, blm, nullptr, 0, VOCAB);
}